// round 15
// baseline (speedup 1.0000x reference)
#include <cuda_runtime.h>
#include <cstddef>

// Problem constants (fixed by the reference)
constexpr int CB   = 64;    // batch
constexpr int CP   = 2048;  // points
constexpr int CK   = 16;    // neighbors
constexpr int CDIM = 3;
constexpr int CNC  = 16;    // rbf centers
constexpr int CSFD = 64;    // spatial feature dim
constexpr int COUT = 64;    // output features
constexpr int FPP  = CK * CDIM;  // 48 floats of features per point

// Scratch for the intermediate x = feature_layer * spatial_sum  (33.5 MB)
__device__ float g_x[(size_t)CB * CP * CSFD];

// ============================ Kernel 1: produce x ===========================
// 1 point per warp, 8 points per 256-thread block. Tiny register footprint ->
// high occupancy -> deep LDG pipeline on the 537MB spatial stream.
constexpr int K1_PTS = 8;

__global__ __launch_bounds__(256, 5)
void rbfn_phase1_kernel(const float* __restrict__ features,
                        const float* __restrict__ spatial,
                        const float* __restrict__ centers,
                        const float* __restrict__ rbfw)
{
    __shared__ float rbfn_sh[CNC * CSFD];        // 4 KB
    __shared__ float cen_sh[CDIM * CNC];         // 192 B
    __shared__ float feat_sh[K1_PTS * CK * 4];   // 2 KB, padded float4 per k

    const int tid = threadIdx.x;
    const int b   = blockIdx.y;
    const int p0  = blockIdx.x * K1_PTS;

    // ---- stage rbfn weights + centers + this block's features ----
    reinterpret_cast<float4*>(rbfn_sh)[tid] =
        reinterpret_cast<const float4*>(rbfw)[tid];   // 256 float4 exactly

    if (tid < K1_PTS * FPP / 4) {   // 96 float4
        float4 v = reinterpret_cast<const float4*>(
            features + ((size_t)b * CP + p0) * FPP)[tid];
        int f0 = 4 * tid;
        #pragma unroll
        for (int e = 0; e < 4; e++) {
            int f  = f0 + e;
            int pt = f / FPP;
            int r  = f - pt * FPP;
            int k  = r / 3;
            int d  = r - k * 3;
            float val = (e == 0) ? v.x : (e == 1) ? v.y : (e == 2) ? v.z : v.w;
            feat_sh[(pt * CK + k) * 4 + d] = val;
        }
    }
    if (tid < CDIM * CNC) cen_sh[tid] = centers[tid];
    __syncthreads();

    const int warp = tid >> 5;
    const int lane = tid & 31;
    const int cg   = lane & 15;   // column group (s = 4*cg..4*cg+3) AND center id
    const int half = lane >> 4;   // which half of the K rows this lane covers

    const size_t pidx = (size_t)b * CP + p0 + warp;

    // --- 1a: spatial sum over K: 256 float4, coalesced, 8 per lane ---
    float sx = 0.f, sy = 0.f, sz = 0.f, sw = 0.f;
    {
        const float4* spv = reinterpret_cast<const float4*>(spatial + pidx * (CK * CSFD));
        #pragma unroll
        for (int i = 0; i < 8; i++) {
            float4 v = spv[i * 32 + lane];
            sx += v.x; sy += v.y; sz += v.z; sw += v.w;
        }
    }
    sx += __shfl_xor_sync(0xffffffffu, sx, 16);
    sy += __shfl_xor_sync(0xffffffffu, sy, 16);
    sz += __shfl_xor_sync(0xffffffffu, sz, 16);
    sw += __shfl_xor_sync(0xffffffffu, sw, 16);

    // --- 1b: RBF sums. lane -> center cg, covers 8 k's of its half ---
    const float c0 = cen_sh[0 * CNC + cg];
    const float c1 = cen_sh[1 * CNC + cg];
    const float c2 = cen_sh[2 * CNC + cg];

    float racc = 0.f;
    #pragma unroll
    for (int i = 0; i < 8; i++) {
        const int k = 2 * i + half;
        float4 fv = reinterpret_cast<const float4*>(feat_sh)[warp * CK + k];
        float d0 = fv.x - c0, d1 = fv.y - c1, d2 = fv.z - c2;
        racc += __expf((d0 * d0 + d1 * d1 + d2 * d2) * -12.5f);
    }
    racc += __shfl_xor_sync(0xffffffffu, racc, 16);
    // lane c (and c+16) now holds rbf_sum for center c

    // --- 1c: feature layer for s = 4*cg..4*cg+3, fused with spatial ---
    float flx = 0.f, fly = 0.f, flz = 0.f, flw = 0.f;
    #pragma unroll
    for (int c = 0; c < CNC; c++) {
        float4 wv = reinterpret_cast<const float4*>(rbfn_sh)[c * 16 + cg];
        float rv  = __shfl_sync(0xffffffffu, racc, c);
        flx += rv * wv.x; fly += rv * wv.y; flz += rv * wv.z; flw += rv * wv.w;
    }
    if (half == 0) {
        float4 xv;
        xv.x = flx * sx; xv.y = fly * sy; xv.z = flz * sz; xv.w = flw * sw;
        reinterpret_cast<float4*>(g_x)[pidx * 16 + cg] = xv;   // 256B/warp, coalesced
    }
}

// ===================== Kernel 2: out[b] = x[b] @ w[b] =======================
// 64 points per 256-thread block; w + x tiles staged in smem; proven R14
// phase-2 load patterns (w: LDS.32 all-distinct, x: LDS.128 uniform broadcast).
constexpr int K2_PTS = 64;

__global__ __launch_bounds__(256, 4)
void rbfn_phase2_kernel(const float* __restrict__ w,
                        float* __restrict__ out)
{
    __shared__ float w_sh[CSFD * COUT];    // 16 KB
    __shared__ float x_sh[K2_PTS * CSFD];  // 16 KB

    const int tid = threadIdx.x;
    const int b   = blockIdx.y;
    const int p0  = blockIdx.x * K2_PTS;

    {
        const float4* wsrc = reinterpret_cast<const float4*>(w + (size_t)b * CSFD * COUT);
        const float4* xsrc = reinterpret_cast<const float4*>(g_x + ((size_t)b * CP + p0) * CSFD);
        #pragma unroll
        for (int i = 0; i < 4; i++) {
            reinterpret_cast<float4*>(w_sh)[tid + i * 256] = wsrc[tid + i * 256];
            reinterpret_cast<float4*>(x_sh)[tid + i * 256] = xsrc[tid + i * 256];
        }
    }
    __syncthreads();

    const int o  = tid & 63;
    const int pg = tid >> 6;   // 0..3, each group handles 16 points

    float acc[16];
    #pragma unroll
    for (int jj = 0; jj < 16; jj++) acc[jj] = 0.f;

    #pragma unroll
    for (int sq = 0; sq < CSFD / 4; sq++) {
        float w0 = w_sh[(4 * sq + 0) * COUT + o];
        float w1 = w_sh[(4 * sq + 1) * COUT + o];
        float w2 = w_sh[(4 * sq + 2) * COUT + o];
        float w3 = w_sh[(4 * sq + 3) * COUT + o];
        #pragma unroll
        for (int jj = 0; jj < 16; jj++) {
            float4 xv = reinterpret_cast<const float4*>(x_sh)[(pg * 16 + jj) * 16 + sq];
            acc[jj] += xv.x * w0 + xv.y * w1 + xv.z * w2 + xv.w * w3;
        }
    }

    float* ob = out + ((size_t)b * CP + p0) * COUT;
    #pragma unroll
    for (int jj = 0; jj < 16; jj++)
        ob[(size_t)(pg * 16 + jj) * COUT + o] = acc[jj];
}

extern "C" void kernel_launch(void* const* d_in, const int* in_sizes, int n_in,
                              void* d_out, int out_size)
{
    const float* features = (const float*)d_in[0];
    const float* spatial  = (const float*)d_in[1];
    const float* centers  = (const float*)d_in[2];
    const float* rbfw     = (const float*)d_in[3];
    const float* w        = (const float*)d_in[4];
    // d_in[5] is K (=16), fixed at compile time
    float* out = (float*)d_out;

    dim3 g1(CP / K1_PTS, CB);
    rbfn_phase1_kernel<<<g1, 256>>>(features, spatial, centers, rbfw);

    dim3 g2(CP / K2_PTS, CB);
    rbfn_phase2_kernel<<<g2, 256>>>(w, out);
}

// round 16
// speedup vs baseline: 1.1839x; 1.1839x over previous
#include <cuda_runtime.h>
#include <cstddef>

// Problem constants (fixed by the reference)
constexpr int CB   = 64;    // batch
constexpr int CP   = 2048;  // points
constexpr int CK   = 16;    // neighbors
constexpr int CDIM = 3;
constexpr int CNC  = 16;    // rbf centers
constexpr int CSFD = 64;    // spatial feature dim
constexpr int COUT = 64;    // output features

constexpr int PTS     = 32;   // points per block
constexpr int THREADS = 256;  // 8 warps; phase 1: 2 pts/warp x 2 sequential passes
constexpr int FPP     = CK * CDIM;  // 48 floats of features per point

__global__ __launch_bounds__(THREADS, 4)
void rbfn_fused_kernel(const float* __restrict__ features,
                       const float* __restrict__ spatial,
                       const float* __restrict__ centers,
                       const float* __restrict__ rbfw,
                       const float* __restrict__ w,
                       float* __restrict__ out)
{
    __shared__ float w_sh[CSFD * COUT];        // 16 KB : w[b] slice
    __shared__ float rbfn_sh[CNC * CSFD];      // 4 KB
    __shared__ float cen_sh[CDIM * CNC];       // 192 B
    __shared__ float x_sh[PTS * CSFD];         // 8 KB : fused x = fl * sp_sum
    __shared__ float feat_sh[PTS * CK * 4];    // 8 KB : features padded to float4/k

    const int tid = threadIdx.x;
    const int b   = blockIdx.y;
    const int p0  = blockIdx.x * PTS;

    // ---- stage per-batch weight slice + constants + features into smem ----
    {
        const float4* wsrc = reinterpret_cast<const float4*>(w + (size_t)b * CSFD * COUT);
        float4* wdst = reinterpret_cast<float4*>(w_sh);
        #pragma unroll
        for (int i = 0; i < (CSFD * COUT / 4) / THREADS; i++)   // 4 iters
            wdst[tid + i * THREADS] = wsrc[tid + i * THREADS];

        reinterpret_cast<float4*>(rbfn_sh)[tid] =
            reinterpret_cast<const float4*>(rbfw)[tid];   // 256 float4 exactly

        // features: 32 pts x 48 floats = 384 float4, scatter to padded [pt][k][4]
        #pragma unroll
        for (int i = tid; i < PTS * FPP / 4; i += THREADS) {
            float4 v = reinterpret_cast<const float4*>(
                features + ((size_t)b * CP + p0) * FPP)[i];
            int f0 = 4 * i;
            #pragma unroll
            for (int e = 0; e < 4; e++) {
                int f  = f0 + e;
                int pt = f / FPP;
                int r  = f - pt * FPP;
                int k  = r / 3;
                int d  = r - k * 3;
                float val = (e == 0) ? v.x : (e == 1) ? v.y : (e == 2) ? v.z : v.w;
                feat_sh[(pt * CK + k) * 4 + d] = val;
            }
        }

        if (tid < CDIM * CNC) cen_sh[tid] = centers[tid];
    }
    __syncthreads();

    const int warp = tid >> 5;
    const int lane = tid & 31;
    const int cg   = lane & 15;   // column group (s = 4*cg..4*cg+3) AND center id
    const int half = lane >> 4;   // which half of the K rows this lane covers

    // ---- Phase 1: two SEQUENTIAL passes of 2 points per warp ----
    // unroll 1: only one pass's live set exists at a time (register pressure)
    #pragma unroll 1
    for (int pass = 0; pass < 2; pass++) {
        const int ptb = warp * 4 + pass * 2;   // local point base for this pass

        // --- 1a: spatial sums, 2 points interleaved ---
        float sx0 = 0.f, sy0 = 0.f, sz0 = 0.f, sw0 = 0.f;
        float sx1 = 0.f, sy1 = 0.f, sz1 = 0.f, sw1 = 0.f;

        const float4* spv = reinterpret_cast<const float4*>(
            spatial + ((size_t)b * CP + p0 + ptb) * (CK * CSFD));
        #pragma unroll
        for (int i = 0; i < 8; i++) {
            float4 v0 = spv[i * 32 + lane];
            float4 v1 = spv[256 + i * 32 + lane];
            sx0 += v0.x; sy0 += v0.y; sz0 += v0.z; sw0 += v0.w;
            sx1 += v1.x; sy1 += v1.y; sz1 += v1.z; sw1 += v1.w;
        }
        sx0 += __shfl_xor_sync(0xffffffffu, sx0, 16);
        sy0 += __shfl_xor_sync(0xffffffffu, sy0, 16);
        sz0 += __shfl_xor_sync(0xffffffffu, sz0, 16);
        sw0 += __shfl_xor_sync(0xffffffffu, sw0, 16);
        sx1 += __shfl_xor_sync(0xffffffffu, sx1, 16);
        sy1 += __shfl_xor_sync(0xffffffffu, sy1, 16);
        sz1 += __shfl_xor_sync(0xffffffffu, sz1, 16);
        sw1 += __shfl_xor_sync(0xffffffffu, sw1, 16);

        // --- 1b: RBF sums. lane -> center cg, covers 8 k's of its half ---
        const float c0 = cen_sh[0 * CNC + cg];
        const float c1 = cen_sh[1 * CNC + cg];
        const float c2 = cen_sh[2 * CNC + cg];

        float racc0 = 0.f, racc1 = 0.f;
        #pragma unroll
        for (int i = 0; i < 8; i++) {
            const int k = 2 * i + half;
            float4 f0 = reinterpret_cast<const float4*>(feat_sh)[(ptb + 0) * CK + k];
            float4 f1 = reinterpret_cast<const float4*>(feat_sh)[(ptb + 1) * CK + k];
            float a0 = f0.x - c0, a1 = f0.y - c1, a2 = f0.z - c2;
            float b0 = f1.x - c0, b1 = f1.y - c1, b2 = f1.z - c2;
            racc0 += __expf((a0 * a0 + a1 * a1 + a2 * a2) * -12.5f);
            racc1 += __expf((b0 * b0 + b1 * b1 + b2 * b2) * -12.5f);
        }
        racc0 += __shfl_xor_sync(0xffffffffu, racc0, 16);
        racc1 += __shfl_xor_sync(0xffffffffu, racc1, 16);
        // lane c (and c+16) now holds rbf_sum for center c

        // --- 1c: feature layer; warp-half h computes point ptb+h ---
        // The 4-wf rbfn LDS.128 now serves TWO points; FMA count halves.
        const float spx = half ? sx1 : sx0;
        const float spy = half ? sy1 : sy0;
        const float spz = half ? sz1 : sz0;
        const float spw = half ? sw1 : sw0;

        float flx = 0.f, fly = 0.f, flz = 0.f, flw = 0.f;
        #pragma unroll
        for (int c = 0; c < CNC; c++) {
            float4 wv = reinterpret_cast<const float4*>(rbfn_sh)[c * 16 + cg];
            float r0 = __shfl_sync(0xffffffffu, racc0, c);
            float r1 = __shfl_sync(0xffffffffu, racc1, c);
            float rv = half ? r1 : r0;
            flx += rv * wv.x; fly += rv * wv.y; flz += rv * wv.z; flw += rv * wv.w;
        }
        {
            float4 xv;
            xv.x = flx * spx; xv.y = fly * spy; xv.z = flz * spz; xv.w = flw * spw;
            reinterpret_cast<float4*>(x_sh)[(ptb + half) * 16 + cg] = xv;
        }
    }
    __syncthreads();

    // ---- Phase 2: out[pt][o] = sum_s x[pt][s] * w_sh[s][o], 8 pts/thread ----
    // (R11-proven: w via LDS.32 all-distinct, x via LDS.128 uniform broadcast)
    const int o  = tid & 63;
    const int pg = tid >> 6;   // 0..3, each group handles 8 points

    float acc[8];
    #pragma unroll
    for (int jj = 0; jj < 8; jj++) acc[jj] = 0.f;

    #pragma unroll
    for (int sq = 0; sq < CSFD / 4; sq++) {
        float w0 = w_sh[(4 * sq + 0) * COUT + o];
        float w1 = w_sh[(4 * sq + 1) * COUT + o];
        float w2 = w_sh[(4 * sq + 2) * COUT + o];
        float w3 = w_sh[(4 * sq + 3) * COUT + o];
        #pragma unroll
        for (int jj = 0; jj < 8; jj++) {
            // warp-uniform address -> smem broadcast (1 wavefront)
            float4 xv = reinterpret_cast<const float4*>(x_sh)[(pg * 8 + jj) * 16 + sq];
            acc[jj] += xv.x * w0 + xv.y * w1 + xv.z * w2 + xv.w * w3;
        }
    }

    float* ob = out + ((size_t)b * CP + p0) * COUT;
    #pragma unroll
    for (int jj = 0; jj < 8; jj++)
        ob[(size_t)(pg * 8 + jj) * COUT + o] = acc[jj];
}

extern "C" void kernel_launch(void* const* d_in, const int* in_sizes, int n_in,
                              void* d_out, int out_size)
{
    const float* features = (const float*)d_in[0];
    const float* spatial  = (const float*)d_in[1];
    const float* centers  = (const float*)d_in[2];
    const float* rbfw     = (const float*)d_in[3];
    const float* w        = (const float*)d_in[4];
    // d_in[5] is K (=16), fixed at compile time
    float* out = (float*)d_out;

    dim3 grid(CP / PTS, CB);
    rbfn_fused_kernel<<<grid, THREADS>>>(features, spatial, centers, rbfw, w, out);
}

// round 17
// speedup vs baseline: 1.3527x; 1.1426x over previous
#include <cuda_runtime.h>
#include <cstddef>

// Problem constants (fixed by the reference)
constexpr int CB   = 64;    // batch
constexpr int CP   = 2048;  // points
constexpr int CK   = 16;    // neighbors
constexpr int CDIM = 3;
constexpr int CNC  = 16;    // rbf centers
constexpr int CSFD = 64;    // spatial feature dim
constexpr int COUT = 64;    // output features

constexpr int PTS     = 32;   // points per block
constexpr int THREADS = 256;  // 8 warps; phase 1: 2 pts/warp x 2 sequential passes
constexpr int FPP     = CK * CDIM;  // 48 floats of features per point

__global__ __launch_bounds__(THREADS, 4)
void rbfn_fused_kernel(const float* __restrict__ features,
                       const float* __restrict__ spatial,
                       const float* __restrict__ centers,
                       const float* __restrict__ rbfw,
                       const float* __restrict__ w,
                       float* __restrict__ out)
{
    __shared__ float w_sh[CSFD * COUT];        // 16 KB : w[b] slice
    __shared__ float rbfn_sh[CNC * CSFD];      // 4 KB
    __shared__ float cen_sh[CDIM * CNC];       // 192 B
    __shared__ float x_sh[PTS * CSFD];         // 8 KB : fused x = fl * sp_sum
    __shared__ float feat_sh[PTS * CK * 4];    // 8 KB : features; reused as
                                               //        phase-2 partial scratch

    const int tid = threadIdx.x;
    const int b   = blockIdx.y;
    const int p0  = blockIdx.x * PTS;

    // ---- stage per-batch weight slice + constants + features into smem ----
    {
        const float4* wsrc = reinterpret_cast<const float4*>(w + (size_t)b * CSFD * COUT);
        float4* wdst = reinterpret_cast<float4*>(w_sh);
        #pragma unroll
        for (int i = 0; i < (CSFD * COUT / 4) / THREADS; i++)   // 4 iters
            wdst[tid + i * THREADS] = wsrc[tid + i * THREADS];

        reinterpret_cast<float4*>(rbfn_sh)[tid] =
            reinterpret_cast<const float4*>(rbfw)[tid];   // 256 float4 exactly

        // features: 32 pts x 48 floats = 384 float4, scatter to padded [pt][k][4]
        #pragma unroll
        for (int i = tid; i < PTS * FPP / 4; i += THREADS) {
            float4 v = reinterpret_cast<const float4*>(
                features + ((size_t)b * CP + p0) * FPP)[i];
            int f0 = 4 * i;
            #pragma unroll
            for (int e = 0; e < 4; e++) {
                int f  = f0 + e;
                int pt = f / FPP;
                int r  = f - pt * FPP;
                int k  = r / 3;
                int d  = r - k * 3;
                float val = (e == 0) ? v.x : (e == 1) ? v.y : (e == 2) ? v.z : v.w;
                feat_sh[(pt * CK + k) * 4 + d] = val;
            }
        }

        if (tid < CDIM * CNC) cen_sh[tid] = centers[tid];
    }
    __syncthreads();

    const int warp = tid >> 5;
    const int lane = tid & 31;
    const int cg   = lane & 15;   // column group (s = 4*cg..4*cg+3) AND center id
    const int half = lane >> 4;   // which half of the K rows this lane covers

    // ---- Phase 1: two SEQUENTIAL passes of 2 points per warp ----
    // unroll 1: only one pass's live set exists at a time (register pressure)
    #pragma unroll 1
    for (int pass = 0; pass < 2; pass++) {
        const int ptb = warp * 4 + pass * 2;   // local point base for this pass

        // --- 1a: spatial sums, 2 points interleaved; streaming loads ---
        float sx0 = 0.f, sy0 = 0.f, sz0 = 0.f, sw0 = 0.f;
        float sx1 = 0.f, sy1 = 0.f, sz1 = 0.f, sw1 = 0.f;

        const float4* spv = reinterpret_cast<const float4*>(
            spatial + ((size_t)b * CP + p0 + ptb) * (CK * CSFD));
        #pragma unroll
        for (int i = 0; i < 8; i++) {
            float4 v0 = __ldcs(&spv[i * 32 + lane]);
            float4 v1 = __ldcs(&spv[256 + i * 32 + lane]);
            sx0 += v0.x; sy0 += v0.y; sz0 += v0.z; sw0 += v0.w;
            sx1 += v1.x; sy1 += v1.y; sz1 += v1.z; sw1 += v1.w;
        }
        sx0 += __shfl_xor_sync(0xffffffffu, sx0, 16);
        sy0 += __shfl_xor_sync(0xffffffffu, sy0, 16);
        sz0 += __shfl_xor_sync(0xffffffffu, sz0, 16);
        sw0 += __shfl_xor_sync(0xffffffffu, sw0, 16);
        sx1 += __shfl_xor_sync(0xffffffffu, sx1, 16);
        sy1 += __shfl_xor_sync(0xffffffffu, sy1, 16);
        sz1 += __shfl_xor_sync(0xffffffffu, sz1, 16);
        sw1 += __shfl_xor_sync(0xffffffffu, sw1, 16);

        // --- 1b: RBF sums. lane -> center cg, covers 8 k's of its half ---
        const float c0 = cen_sh[0 * CNC + cg];
        const float c1 = cen_sh[1 * CNC + cg];
        const float c2 = cen_sh[2 * CNC + cg];

        float racc0 = 0.f, racc1 = 0.f;
        #pragma unroll
        for (int i = 0; i < 8; i++) {
            const int k = 2 * i + half;
            float4 f0 = reinterpret_cast<const float4*>(feat_sh)[(ptb + 0) * CK + k];
            float4 f1 = reinterpret_cast<const float4*>(feat_sh)[(ptb + 1) * CK + k];
            float a0 = f0.x - c0, a1 = f0.y - c1, a2 = f0.z - c2;
            float b0 = f1.x - c0, b1 = f1.y - c1, b2 = f1.z - c2;
            racc0 += __expf((a0 * a0 + a1 * a1 + a2 * a2) * -12.5f);
            racc1 += __expf((b0 * b0 + b1 * b1 + b2 * b2) * -12.5f);
        }
        racc0 += __shfl_xor_sync(0xffffffffu, racc0, 16);
        racc1 += __shfl_xor_sync(0xffffffffu, racc1, 16);
        // lane c (and c+16) now holds rbf_sum for center c

        // --- 1c: feature layer; warp-half h computes point ptb+h ---
        const float spx = half ? sx1 : sx0;
        const float spy = half ? sy1 : sy0;
        const float spz = half ? sz1 : sz0;
        const float spw = half ? sw1 : sw0;

        float flx = 0.f, fly = 0.f, flz = 0.f, flw = 0.f;
        #pragma unroll
        for (int c = 0; c < CNC; c++) {
            float4 wv = reinterpret_cast<const float4*>(rbfn_sh)[c * 16 + cg];
            float r0 = __shfl_sync(0xffffffffu, racc0, c);
            float r1 = __shfl_sync(0xffffffffu, racc1, c);
            float rv = half ? r1 : r0;
            flx += rv * wv.x; fly += rv * wv.y; flz += rv * wv.z; flw += rv * wv.w;
        }
        {
            float4 xv;
            xv.x = flx * spx; xv.y = fly * spy; xv.z = flz * spz; xv.w = flw * spw;
            reinterpret_cast<float4*>(x_sh)[(ptb + half) * 16 + cg] = xv;
        }
    }
    __syncthreads();   // x_sh ready; feat_sh dead -> reusable as scratch

    // ---- Phase 2: out[pt][o] = sum_s x[pt][s] * w_sh[s][o] ----
    // warp = (pts-group pgrp: 8 pts) x (sq-half sqh: 8 of 16 sq).
    // Each warp covers ALL 64 o (lane and lane+32) for its half of s.
    // Partials combined through feat_sh scratch.
    const int pgrp = warp & 3;
    const int sqh  = warp >> 2;

    float acc0[8], acc1[8];
    #pragma unroll
    for (int jj = 0; jj < 8; jj++) { acc0[jj] = 0.f; acc1[jj] = 0.f; }

    #pragma unroll
    for (int si = 0; si < 8; si++) {
        const int sq = sqh * 8 + si;
        float wa0 = w_sh[(4 * sq + 0) * COUT + lane];
        float wb0 = w_sh[(4 * sq + 0) * COUT + lane + 32];
        float wa1 = w_sh[(4 * sq + 1) * COUT + lane];
        float wb1 = w_sh[(4 * sq + 1) * COUT + lane + 32];
        float wa2 = w_sh[(4 * sq + 2) * COUT + lane];
        float wb2 = w_sh[(4 * sq + 2) * COUT + lane + 32];
        float wa3 = w_sh[(4 * sq + 3) * COUT + lane];
        float wb3 = w_sh[(4 * sq + 3) * COUT + lane + 32];
        #pragma unroll
        for (int jj = 0; jj < 8; jj++) {
            // warp-uniform address -> smem broadcast (1 wavefront)
            float4 xv = reinterpret_cast<const float4*>(x_sh)[(pgrp * 8 + jj) * 16 + sq];
            acc0[jj] += xv.x * wa0 + xv.y * wa1 + xv.z * wa2 + xv.w * wa3;
            acc1[jj] += xv.x * wb0 + xv.y * wb1 + xv.z * wb2 + xv.w * wb3;
        }
    }

    float* scratch = feat_sh;   // 32 pts x 64 o = 2048 floats = exact fit
    if (sqh == 0) {
        #pragma unroll
        for (int jj = 0; jj < 8; jj++) {
            scratch[(pgrp * 8 + jj) * COUT + lane]      = acc0[jj];
            scratch[(pgrp * 8 + jj) * COUT + lane + 32] = acc1[jj];
        }
    }
    __syncthreads();
    if (sqh == 1) {
        float* ob = out + ((size_t)b * CP + p0) * COUT;
        #pragma unroll
        for (int jj = 0; jj < 8; jj++) {
            const int pt = pgrp * 8 + jj;
            ob[(size_t)pt * COUT + lane]      = acc0[jj] + scratch[pt * COUT + lane];
            ob[(size_t)pt * COUT + lane + 32] = acc1[jj] + scratch[pt * COUT + lane + 32];
        }
    }
}

extern "C" void kernel_launch(void* const* d_in, const int* in_sizes, int n_in,
                              void* d_out, int out_size)
{
    const float* features = (const float*)d_in[0];
    const float* spatial  = (const float*)d_in[1];
    const float* centers  = (const float*)d_in[2];
    const float* rbfw     = (const float*)d_in[3];
    const float* w        = (const float*)d_in[4];
    // d_in[5] is K (=16), fixed at compile time
    float* out = (float*)d_out;

    dim3 grid(CP / PTS, CB);
    rbfn_fused_kernel<<<grid, THREADS>>>(features, spatial, centers, rbfw, w, out);
}